// round 8
// baseline (speedup 1.0000x reference)
#include <cuda_runtime.h>
#include <cuda_bf16.h>
#include <math_constants.h>

// Shapes fixed by the dataset instance:
//   xyz:        [B,3,N] float32   B=4, N=16384
//   sparse_xyz: [B,3,M] float32   M=4096
//   sparse_flow:[B,3,M] float32
//   resol_factor: int32 scalar, K: int32 scalar (5)
//   out:        [B,3,N] float32
#define BDIM 4
#define NDIM 16384
#define MDIM 4096
#define TPB  128
#define QPT  2
#define SMEM_BYTES (MDIM * (int)sizeof(float4))

// Epilogue for one query given its 5 neighbor indices (selection done on the
// expanded metric; here we recompute EXACT distances for the softmax).
__device__ __forceinline__ void finalize5(
    const float4* __restrict__ sp, const float* __restrict__ sflow, int sbase,
    float qx, float qy, float qz, float inv_s2,
    int i0, int i1, int i2, int i3, int i4,
    float& ox, float& oy, float& oz)
{
    int idx[5] = { i0, i1, i2, i3, i4 };
    float e[5];
#pragma unroll
    for (int k = 0; k < 5; ++k) {
        float4 p = sp[idx[k]];
        float dx = p.x - qx, dy = p.y - qy, dz = p.z - qz;
        float sq = fmaf(dx, dx, fmaf(dy, dy, dz * dz));
        e[k] = sqrtf(fmaxf(sq * inv_s2, 1e-12f));
    }
    // min over the 5 (selection used the approx metric; be safe about near-ties)
    float em = fminf(fminf(fminf(e[0], e[1]), fminf(e[2], e[3])), e[4]);

    float w[5], ws = 0.f;
#pragma unroll
    for (int k = 0; k < 5; ++k) { w[k] = __expf(em - e[k]); ws += w[k]; }

    const float* f0 = sflow + sbase;
    const float* f1 = f0 + MDIM;
    const float* f2 = f1 + MDIM;
    float fx = 0.f, fy = 0.f, fz = 0.f;
#pragma unroll
    for (int k = 0; k < 5; ++k) {
        fx = fmaf(w[k], f0[idx[k]], fx);
        fy = fmaf(w[k], f1[idx[k]], fy);
        fz = fmaf(w[k], f2[idx[k]], fz);
    }
    const float inv_w = 1.0f / ws;
    ox = fx * inv_w; oy = fy * inv_w; oz = fz * inv_w;
}

#define INS5(s, j, D0, D1, D2, D3, D4, I0, I1, I2, I3, I4)                         \
    if ((s) < D4) {                                                                \
        D4 = (s); I4 = (j);                                                        \
        if (D4 < D3) { float t = D3; D3 = D4; D4 = t; int ti = I3; I3 = I4; I4 = ti; } \
        if (D3 < D2) { float t = D2; D2 = D3; D3 = t; int ti = I2; I2 = I3; I3 = ti; } \
        if (D2 < D1) { float t = D1; D1 = D2; D2 = t; int ti = I1; I1 = I2; I2 = ti; } \
        if (D1 < D0) { float t = D0; D0 = D1; D1 = t; int ti = I0; I0 = I1; I1 = ti; } \
    }

__global__ __launch_bounds__(TPB) void upsample_flow(
    const float* __restrict__ xyz,
    const float* __restrict__ sxyz,
    const float* __restrict__ sflow,
    const int* __restrict__ resol_ptr,
    const int* __restrict__ K_ptr,
    float* __restrict__ out)
{
    extern __shared__ float4 sp[];  // [MDIM] : (px, py, pz, |p|^2)

    const int b    = blockIdx.y;
    const int tid  = threadIdx.x;
    const int sbase = b * 3 * MDIM;

    // cooperative smem fill (coalesced global reads)
    for (int i = tid; i < MDIM; i += TPB) {
        float px = sxyz[sbase + i];
        float py = sxyz[sbase + MDIM + i];
        float pz = sxyz[sbase + 2 * MDIM + i];
        sp[i] = make_float4(px, py, pz, fmaf(px, px, fmaf(py, py, pz * pz)));
    }
    __syncthreads();

    const int n0 = blockIdx.x * (TPB * QPT) + tid;
    const int n1 = n0 + TPB;
    const int qbase = b * 3 * NDIM;

    const float q0x = xyz[qbase + n0];
    const float q0y = xyz[qbase + NDIM + n0];
    const float q0z = xyz[qbase + 2 * NDIM + n0];
    const float q1x = xyz[qbase + n1];
    const float q1y = xyz[qbase + NDIM + n1];
    const float q1z = xyz[qbase + 2 * NDIM + n1];

    // expanded-metric coefficients: s = |p|^2 - 2 p.q  (|q|^2, sigma dropped: monotonic)
    const float a0x = -2.f * q0x, a0y = -2.f * q0y, a0z = -2.f * q0z;
    const float a1x = -2.f * q1x, a1y = -2.f * q1y, a1z = -2.f * q1z;

    const int   K      = *K_ptr;
    const float sigma  = (float)(*resol_ptr);   // INITIAL_RADIUS = 1.0
    const float inv_s2 = 1.0f / (sigma * sigma);

    if (K == 5) {
        float d00 = CUDART_INF_F, d01 = CUDART_INF_F, d02 = CUDART_INF_F,
              d03 = CUDART_INF_F, d04 = CUDART_INF_F;
        float d10 = CUDART_INF_F, d11 = CUDART_INF_F, d12 = CUDART_INF_F,
              d13 = CUDART_INF_F, d14 = CUDART_INF_F;
        int i00 = 0, i01 = 0, i02 = 0, i03 = 0, i04 = 0;
        int i10 = 0, i11 = 0, i12 = 0, i13 = 0, i14 = 0;

#pragma unroll 4
        for (int j = 0; j < MDIM; ++j) {
            const float4 p = sp[j];
            const float s0 = fmaf(p.x, a0x, fmaf(p.y, a0y, fmaf(p.z, a0z, p.w)));
            const float s1 = fmaf(p.x, a1x, fmaf(p.y, a1y, fmaf(p.z, a1z, p.w)));
            INS5(s0, j, d00, d01, d02, d03, d04, i00, i01, i02, i03, i04);
            INS5(s1, j, d10, d11, d12, d13, d14, i10, i11, i12, i13, i14);
        }

        float ox, oy, oz;
        finalize5(sp, sflow, sbase, q0x, q0y, q0z, inv_s2,
                  i00, i01, i02, i03, i04, ox, oy, oz);
        out[qbase + n0]            = ox;
        out[qbase + NDIM + n0]     = oy;
        out[qbase + 2 * NDIM + n0] = oz;

        finalize5(sp, sflow, sbase, q1x, q1y, q1z, inv_s2,
                  i10, i11, i12, i13, i14, ox, oy, oz);
        out[qbase + n1]            = ox;
        out[qbase + NDIM + n1]     = oy;
        out[qbase + 2 * NDIM + n1] = oz;
    } else {
        // ---- generic fallback, K <= 32 (exact distances; correctness only) ----
        const int KK = (K < 32) ? K : 32;
#pragma unroll
        for (int qq = 0; qq < QPT; ++qq) {
            const int n = (qq == 0) ? n0 : n1;
            const float qx = (qq == 0) ? q0x : q1x;
            const float qy = (qq == 0) ? q0y : q1y;
            const float qz = (qq == 0) ? q0z : q1z;

            float dl[32];
            int   il[32];
            for (int k = 0; k < KK; ++k) { dl[k] = CUDART_INF_F; il[k] = 0; }
            for (int j = 0; j < MDIM; ++j) {
                const float4 p = sp[j];
                const float dx = p.x - qx, dy = p.y - qy, dz = p.z - qz;
                const float sq = fmaf(dx, dx, fmaf(dy, dy, dz * dz));
                if (sq < dl[KK - 1]) {
                    int k = KK - 1;
                    while (k > 0 && dl[k - 1] > sq) {
                        dl[k] = dl[k - 1]; il[k] = il[k - 1]; --k;
                    }
                    dl[k] = sq; il[k] = j;
                }
            }
            const float em = sqrtf(fmaxf(dl[0] * inv_s2, 1e-12f));
            float fx = 0.f, fy = 0.f, fz = 0.f, wsum = 0.f;
            for (int k = 0; k < KK; ++k) {
                const float e = sqrtf(fmaxf(dl[k] * inv_s2, 1e-12f));
                const float w = __expf(em - e);
                wsum += w;
                const int idx = il[k];
                fx += w * sflow[sbase + idx];
                fy += w * sflow[sbase + MDIM + idx];
                fz += w * sflow[sbase + 2 * MDIM + idx];
            }
            const float inv_w = 1.0f / wsum;
            out[qbase + n]            = fx * inv_w;
            out[qbase + NDIM + n]     = fy * inv_w;
            out[qbase + 2 * NDIM + n] = fz * inv_w;
        }
    }
}

extern "C" void kernel_launch(void* const* d_in, const int* in_sizes, int n_in,
                              void* d_out, int out_size)
{
    const float* xyz   = (const float*)d_in[0];
    const float* sxyz  = (const float*)d_in[1];
    const float* sflow = (const float*)d_in[2];
    const int*   resol = (const int*)d_in[3];
    const int*   Kp    = (const int*)d_in[4];
    float* out = (float*)d_out;

    // 64 KB dynamic smem needs an explicit opt-in (idempotent; not a stream op,
    // so it's safe under graph capture).
    cudaFuncSetAttribute(upsample_flow,
                         cudaFuncAttributeMaxDynamicSharedMemorySize, SMEM_BYTES);

    dim3 grid(NDIM / (TPB * QPT), BDIM);
    upsample_flow<<<grid, TPB, SMEM_BYTES>>>(xyz, sxyz, sflow, resol, Kp, out);
}

// round 9
// speedup vs baseline: 1.3512x; 1.3512x over previous
#include <cuda_runtime.h>
#include <cuda_bf16.h>
#include <math_constants.h>

// Shapes fixed by the dataset instance:
//   xyz:        [B,3,N] float32   B=4, N=16384
//   sparse_xyz: [B,3,M] float32   M=4096
//   sparse_flow:[B,3,M] float32
//   resol_factor: int32 scalar, K: int32 scalar (5)
//   out:        [B,3,N] float32
#define BDIM 4
#define NDIM 16384
#define MDIM 4096
#define TPB  256
#define QPC  (TPB / 2)            // queries per CTA (2 lanes per query)
#define SMEM_BYTES (MDIM * (int)sizeof(float4))

#define INS5(s, j, D0, D1, D2, D3, D4, I0, I1, I2, I3, I4)                             \
    if ((s) < D4) {                                                                    \
        D4 = (s); I4 = (j);                                                            \
        if (D4 < D3) { float t = D3; D3 = D4; D4 = t; int ti = I3; I3 = I4; I4 = ti; } \
        if (D3 < D2) { float t = D2; D2 = D3; D3 = t; int ti = I2; I2 = I3; I3 = ti; } \
        if (D2 < D1) { float t = D1; D1 = D2; D2 = t; int ti = I1; I1 = I2; I2 = ti; } \
        if (D1 < D0) { float t = D0; D0 = D1; D1 = t; int ti = I0; I0 = I1; I1 = ti; } \
    }

__global__ __launch_bounds__(TPB) void upsample_flow(
    const float* __restrict__ xyz,
    const float* __restrict__ sxyz,
    const float* __restrict__ sflow,
    const int* __restrict__ resol_ptr,
    const int* __restrict__ K_ptr,
    float* __restrict__ out)
{
    extern __shared__ float4 sp[];  // [MDIM] : (px, py, pz, unused)

    const int b     = blockIdx.y;
    const int tid   = threadIdx.x;
    const int sbase = b * 3 * MDIM;

    // cooperative smem fill (coalesced global reads)
    for (int i = tid; i < MDIM; i += TPB) {
        float px = sxyz[sbase + i];
        float py = sxyz[sbase + MDIM + i];
        float pz = sxyz[sbase + 2 * MDIM + i];
        sp[i] = make_float4(px, py, pz, 0.f);
    }
    __syncthreads();

    // Two lanes (even/odd) share one query; each scans half of M.
    const int half  = tid & 1;                       // 0 or 1
    const int n     = blockIdx.x * QPC + (tid >> 1); // query index
    const int qbase = b * 3 * NDIM;

    const float qx = xyz[qbase + n];
    const float qy = xyz[qbase + NDIM + n];
    const float qz = xyz[qbase + 2 * NDIM + n];

    const int   K      = *K_ptr;
    const float sigma  = (float)(*resol_ptr);   // INITIAL_RADIUS = 1.0
    const float inv_s2 = 1.0f / (sigma * sigma);

    if (K == 5) {
        float d0 = CUDART_INF_F, d1 = CUDART_INF_F, d2 = CUDART_INF_F,
              d3 = CUDART_INF_F, d4 = CUDART_INF_F;
        int   i0 = 0, i1 = 0, i2 = 0, i3 = 0, i4 = 0;

        const int jbeg = half * (MDIM / 2);
        const int jend = jbeg + (MDIM / 2);

#pragma unroll 8
        for (int j = jbeg; j < jend; ++j) {
            const float4 p  = sp[j];
            const float  dx = p.x - qx;
            const float  dy = p.y - qy;
            const float  dz = p.z - qz;
            const float  sq = fmaf(dx, dx, fmaf(dy, dy, dz * dz));
            INS5(sq, j, d0, d1, d2, d3, d4, i0, i1, i2, i3, i4);
        }

        // merge partner lane's sorted top-5 into mine (exchange via shfl, then insert)
        const unsigned fullm = 0xFFFFFFFFu;
        float pd0 = __shfl_xor_sync(fullm, d0, 1);
        float pd1 = __shfl_xor_sync(fullm, d1, 1);
        float pd2 = __shfl_xor_sync(fullm, d2, 1);
        float pd3 = __shfl_xor_sync(fullm, d3, 1);
        float pd4 = __shfl_xor_sync(fullm, d4, 1);
        int   pi0 = __shfl_xor_sync(fullm, i0, 1);
        int   pi1 = __shfl_xor_sync(fullm, i1, 1);
        int   pi2 = __shfl_xor_sync(fullm, i2, 1);
        int   pi3 = __shfl_xor_sync(fullm, i3, 1);
        int   pi4 = __shfl_xor_sync(fullm, i4, 1);

        INS5(pd0, pi0, d0, d1, d2, d3, d4, i0, i1, i2, i3, i4);
        INS5(pd1, pi1, d0, d1, d2, d3, d4, i0, i1, i2, i3, i4);
        INS5(pd2, pi2, d0, d1, d2, d3, d4, i0, i1, i2, i3, i4);
        INS5(pd3, pi3, d0, d1, d2, d3, d4, i0, i1, i2, i3, i4);
        INS5(pd4, pi4, d0, d1, d2, d3, d4, i0, i1, i2, i3, i4);

        // Epilogue: even lane computes + stores (list is sorted; d0 is min).
        if (half == 0) {
            const float e0 = sqrtf(fmaxf(d0 * inv_s2, 1e-12f));
            const float e1 = sqrtf(fmaxf(d1 * inv_s2, 1e-12f));
            const float e2 = sqrtf(fmaxf(d2 * inv_s2, 1e-12f));
            const float e3 = sqrtf(fmaxf(d3 * inv_s2, 1e-12f));
            const float e4 = sqrtf(fmaxf(d4 * inv_s2, 1e-12f));
            const float em = e0;

            const float w0 = __expf(em - e0);
            const float w1 = __expf(em - e1);
            const float w2 = __expf(em - e2);
            const float w3 = __expf(em - e3);
            const float w4 = __expf(em - e4);
            const float inv_w = 1.0f / (w0 + w1 + w2 + w3 + w4);

            const float* f0 = sflow + sbase;
            const float* f1 = f0 + MDIM;
            const float* f2 = f1 + MDIM;
            const float fx = w0*f0[i0] + w1*f0[i1] + w2*f0[i2] + w3*f0[i3] + w4*f0[i4];
            const float fy = w0*f1[i0] + w1*f1[i1] + w2*f1[i2] + w3*f1[i3] + w4*f1[i4];
            const float fz = w0*f2[i0] + w1*f2[i1] + w2*f2[i2] + w3*f2[i3] + w4*f2[i4];

            out[qbase + n]            = fx * inv_w;
            out[qbase + NDIM + n]     = fy * inv_w;
            out[qbase + 2 * NDIM + n] = fz * inv_w;
        }
    } else {
        // ---- generic fallback, K <= 32 (even lane does full scan; correctness only) ----
        if (half == 0) {
            const int KK = (K < 32) ? K : 32;
            float dl[32];
            int   il[32];
            for (int k = 0; k < KK; ++k) { dl[k] = CUDART_INF_F; il[k] = 0; }
            for (int j = 0; j < MDIM; ++j) {
                const float4 p = sp[j];
                const float dx = p.x - qx, dy = p.y - qy, dz = p.z - qz;
                const float sq = fmaf(dx, dx, fmaf(dy, dy, dz * dz));
                if (sq < dl[KK - 1]) {
                    int k = KK - 1;
                    while (k > 0 && dl[k - 1] > sq) {
                        dl[k] = dl[k - 1]; il[k] = il[k - 1]; --k;
                    }
                    dl[k] = sq; il[k] = j;
                }
            }
            const float em = sqrtf(fmaxf(dl[0] * inv_s2, 1e-12f));
            float fx = 0.f, fy = 0.f, fz = 0.f, wsum = 0.f;
            for (int k = 0; k < KK; ++k) {
                const float e = sqrtf(fmaxf(dl[k] * inv_s2, 1e-12f));
                const float w = __expf(em - e);
                wsum += w;
                const int idx = il[k];
                fx += w * sflow[sbase + idx];
                fy += w * sflow[sbase + MDIM + idx];
                fz += w * sflow[sbase + 2 * MDIM + idx];
            }
            const float inv_w = 1.0f / wsum;
            out[qbase + n]            = fx * inv_w;
            out[qbase + NDIM + n]     = fy * inv_w;
            out[qbase + 2 * NDIM + n] = fz * inv_w;
        }
    }
}

extern "C" void kernel_launch(void* const* d_in, const int* in_sizes, int n_in,
                              void* d_out, int out_size)
{
    const float* xyz   = (const float*)d_in[0];
    const float* sxyz  = (const float*)d_in[1];
    const float* sflow = (const float*)d_in[2];
    const int*   resol = (const int*)d_in[3];
    const int*   Kp    = (const int*)d_in[4];
    float* out = (float*)d_out;

    // 64 KB dynamic smem opt-in (idempotent; safe under graph capture).
    cudaFuncSetAttribute(upsample_flow,
                         cudaFuncAttributeMaxDynamicSharedMemorySize, SMEM_BYTES);

    dim3 grid(NDIM / QPC, BDIM);
    upsample_flow<<<grid, TPB, SMEM_BYTES>>>(xyz, sxyz, sflow, resol, Kp, out);
}

// round 11
// speedup vs baseline: 1.3761x; 1.0185x over previous
#include <cuda_runtime.h>
#include <cuda_bf16.h>
#include <math_constants.h>

// Shapes fixed by the dataset instance:
//   xyz:        [B,3,N] float32   B=4, N=16384
//   sparse_xyz: [B,3,M] float32   M=4096
//   sparse_flow:[B,3,M] float32
//   resol_factor: int32 scalar, K: int32 scalar (5)
//   out:        [B,3,N] float32
#define BDIM 4
#define NDIM 16384
#define MDIM 4096
#define TPB  256
#define SPLIT 2
#define MH   (MDIM / SPLIT)       // points per CTA-half = 2048

// Scratch: per query, per half, sorted top-5 (squared dist + index), qid-major.
// Layout: [B*N][SPLIT*5]  -> element (qid*10 + half*5 + k)
__device__ float g_sd[BDIM * NDIM * SPLIT * 5];
__device__ int   g_si[BDIM * NDIM * SPLIT * 5];

#define INS5(s, j, D0, D1, D2, D3, D4, I0, I1, I2, I3, I4)                             \
    if ((s) < D4) {                                                                    \
        D4 = (s); I4 = (j);                                                            \
        if (D4 < D3) { float t = D3; D3 = D4; D4 = t; int ti = I3; I3 = I4; I4 = ti; } \
        if (D3 < D2) { float t = D2; D2 = D3; D3 = t; int ti = I2; I2 = I3; I3 = ti; } \
        if (D2 < D1) { float t = D1; D1 = D2; D2 = t; int ti = I1; I1 = I2; I2 = ti; } \
        if (D1 < D0) { float t = D0; D0 = D1; D1 = t; int ti = I0; I0 = I1; I1 = ti; } \
    }

// ---------------- Kernel 1: half-M scan, top-5 per (query, half) -------------
__global__ __launch_bounds__(TPB) void scan_half(
    const float* __restrict__ xyz,
    const float* __restrict__ sxyz,
    const float* __restrict__ sflow,
    const int* __restrict__ resol_ptr,
    const int* __restrict__ K_ptr,
    float* __restrict__ out)
{
    __shared__ float sx[MH];
    __shared__ float sy[MH];
    __shared__ float sz[MH];

    const int b    = blockIdx.y;
    const int half = blockIdx.x & (SPLIT - 1);
    const int qblk = blockIdx.x >> 1;            // SPLIT==2
    const int tid  = threadIdx.x;
    const int n    = qblk * TPB + tid;

    const int sbase = b * 3 * MDIM;
    const int j0    = half * MH;

    const int K = *K_ptr;

    if (K == 5) {
        // cooperative smem load of this CTA's half of the sparse points
        #pragma unroll
        for (int i = tid; i < MH; i += TPB) {
            sx[i] = sxyz[sbase + j0 + i];
            sy[i] = sxyz[sbase + MDIM + j0 + i];
            sz[i] = sxyz[sbase + 2 * MDIM + j0 + i];
        }
        __syncthreads();

        const int qbase = b * 3 * NDIM;
        const float qx = xyz[qbase + n];
        const float qy = xyz[qbase + NDIM + n];
        const float qz = xyz[qbase + 2 * NDIM + n];

        float d0 = CUDART_INF_F, d1 = CUDART_INF_F, d2 = CUDART_INF_F,
              d3 = CUDART_INF_F, d4 = CUDART_INF_F;
        int   i0 = 0, i1 = 0, i2 = 0, i3 = 0, i4 = 0;

        #pragma unroll 8
        for (int j = 0; j < MH; ++j) {
            const float dx = sx[j] - qx;
            const float dy = sy[j] - qy;
            const float dz = sz[j] - qz;
            float sq = dx * dx;
            sq = fmaf(dy, dy, sq);
            sq = fmaf(dz, dz, sq);
            INS5(sq, j, d0, d1, d2, d3, d4, i0, i1, i2, i3, i4);
        }

        const int qid  = b * NDIM + n;
        const int sidx = qid * (SPLIT * 5) + half * 5;
        g_sd[sidx + 0] = d0;  g_si[sidx + 0] = j0 + i0;
        g_sd[sidx + 1] = d1;  g_si[sidx + 1] = j0 + i1;
        g_sd[sidx + 2] = d2;  g_si[sidx + 2] = j0 + i2;
        g_sd[sidx + 3] = d3;  g_si[sidx + 3] = j0 + i3;
        g_sd[sidx + 4] = d4;  g_si[sidx + 4] = j0 + i4;
    } else if (half == 0) {
        // ---- generic fallback, K <= 32, reads global directly (correctness only) ----
        const float sigma  = (float)(*resol_ptr);   // INITIAL_RADIUS = 1.0
        const float inv_s2 = 1.0f / (sigma * sigma);
        const int qbase = b * 3 * NDIM;
        const float qx = xyz[qbase + n];
        const float qy = xyz[qbase + NDIM + n];
        const float qz = xyz[qbase + 2 * NDIM + n];

        const int KK = (K < 32) ? K : 32;
        float dl[32];
        int   il[32];
        for (int k = 0; k < KK; ++k) { dl[k] = CUDART_INF_F; il[k] = 0; }
        for (int j = 0; j < MDIM; ++j) {
            const float dx = sxyz[sbase + j] - qx;
            const float dy = sxyz[sbase + MDIM + j] - qy;
            const float dz = sxyz[sbase + 2 * MDIM + j] - qz;
            const float sq = fmaf(dx, dx, fmaf(dy, dy, dz * dz));
            if (sq < dl[KK - 1]) {
                int k = KK - 1;
                while (k > 0 && dl[k - 1] > sq) {
                    dl[k] = dl[k - 1]; il[k] = il[k - 1]; --k;
                }
                dl[k] = sq; il[k] = j;
            }
        }
        const float em = sqrtf(fmaxf(dl[0] * inv_s2, 1e-12f));
        float fx = 0.f, fy = 0.f, fz = 0.f, wsum = 0.f;
        for (int k = 0; k < KK; ++k) {
            const float e = sqrtf(fmaxf(dl[k] * inv_s2, 1e-12f));
            const float w = __expf(em - e);
            wsum += w;
            const int idx = il[k];
            fx += w * sflow[sbase + idx];
            fy += w * sflow[sbase + MDIM + idx];
            fz += w * sflow[sbase + 2 * MDIM + idx];
        }
        const float inv_w = 1.0f / wsum;
        out[qbase + n]            = fx * inv_w;
        out[qbase + NDIM + n]     = fy * inv_w;
        out[qbase + 2 * NDIM + n] = fz * inv_w;
    }
}

// ---------------- Kernel 2: merge halves + exact softmax epilogue ------------
__global__ __launch_bounds__(TPB) void merge_final(
    const float* __restrict__ sflow,
    const int* __restrict__ resol_ptr,
    const int* __restrict__ K_ptr,
    float* __restrict__ out)
{
    if (*K_ptr != 5) return;  // fallback path already wrote out in kernel 1

    const int gid = blockIdx.x * TPB + threadIdx.x;   // 0 .. B*N-1
    const int b   = gid / NDIM;
    const int n   = gid - b * NDIM;

    const float sigma  = (float)(*resol_ptr);   // INITIAL_RADIUS = 1.0
    const float inv_s2 = 1.0f / (sigma * sigma);

    const int sidx = gid * (SPLIT * 5);

    // first half's sorted list
    float d0 = g_sd[sidx + 0], d1 = g_sd[sidx + 1], d2 = g_sd[sidx + 2],
          d3 = g_sd[sidx + 3], d4 = g_sd[sidx + 4];
    int   i0 = g_si[sidx + 0], i1 = g_si[sidx + 1], i2 = g_si[sidx + 2],
          i3 = g_si[sidx + 3], i4 = g_si[sidx + 4];

    // insert second half's sorted list
    #pragma unroll
    for (int k = 0; k < 5; ++k) {
        const float pd = g_sd[sidx + 5 + k];
        const int   pi = g_si[sidx + 5 + k];
        INS5(pd, pi, d0, d1, d2, d3, d4, i0, i1, i2, i3, i4);
    }

    const float e0 = sqrtf(fmaxf(d0 * inv_s2, 1e-12f));
    const float e1 = sqrtf(fmaxf(d1 * inv_s2, 1e-12f));
    const float e2 = sqrtf(fmaxf(d2 * inv_s2, 1e-12f));
    const float e3 = sqrtf(fmaxf(d3 * inv_s2, 1e-12f));
    const float e4 = sqrtf(fmaxf(d4 * inv_s2, 1e-12f));
    const float em = e0;  // sorted ascending

    const float w0 = __expf(em - e0);
    const float w1 = __expf(em - e1);
    const float w2 = __expf(em - e2);
    const float w3 = __expf(em - e3);
    const float w4 = __expf(em - e4);
    const float inv_w = 1.0f / (w0 + w1 + w2 + w3 + w4);

    const int sbase = b * 3 * MDIM;
    const float* f0 = sflow + sbase;
    const float* f1 = f0 + MDIM;
    const float* f2 = f1 + MDIM;
    const float fx = w0*f0[i0] + w1*f0[i1] + w2*f0[i2] + w3*f0[i3] + w4*f0[i4];
    const float fy = w0*f1[i0] + w1*f1[i1] + w2*f1[i2] + w3*f1[i3] + w4*f1[i4];
    const float fz = w0*f2[i0] + w1*f2[i1] + w2*f2[i2] + w3*f2[i3] + w4*f2[i4];

    const int qbase = b * 3 * NDIM;
    out[qbase + n]            = fx * inv_w;
    out[qbase + NDIM + n]     = fy * inv_w;
    out[qbase + 2 * NDIM + n] = fz * inv_w;
}

extern "C" void kernel_launch(void* const* d_in, const int* in_sizes, int n_in,
                              void* d_out, int out_size)
{
    const float* xyz   = (const float*)d_in[0];
    const float* sxyz  = (const float*)d_in[1];
    const float* sflow = (const float*)d_in[2];
    const int*   resol = (const int*)d_in[3];
    const int*   Kp    = (const int*)d_in[4];
    float* out = (float*)d_out;

    dim3 grid1(SPLIT * (NDIM / TPB), BDIM);   // 128 x 4 = 512 CTAs
    scan_half<<<grid1, TPB>>>(xyz, sxyz, sflow, resol, Kp, out);

    dim3 grid2((BDIM * NDIM) / TPB);          // 256 CTAs
    merge_final<<<grid2, TPB>>>(sflow, resol, Kp, out);
}

// round 12
// speedup vs baseline: 1.8799x; 1.3661x over previous
#include <cuda_runtime.h>
#include <cuda_bf16.h>
#include <math_constants.h>

// Shapes fixed by the dataset instance:
//   xyz:        [B,3,N] float32   B=4, N=16384
//   sparse_xyz: [B,3,M] float32   M=4096
//   sparse_flow:[B,3,M] float32
//   resol_factor: int32 scalar, K: int32 scalar (5)
//   out:        [B,3,N] float32
#define BDIM 4
#define NDIM 16384
#define MDIM 4096
#define TPB  256

typedef unsigned long long u64;

// ---- packed f32x2 helpers (Blackwell sm_103a; FFMA2/FADD2/FMUL2 in SASS) ----
__device__ __forceinline__ u64 pk2(float lo, float hi) {
    u64 r; asm("mov.b64 %0, {%1, %2};" : "=l"(r) : "f"(lo), "f"(hi)); return r;
}
__device__ __forceinline__ void upk2(u64 v, float& lo, float& hi) {
    asm("mov.b64 {%0, %1}, %2;" : "=f"(lo), "=f"(hi) : "l"(v));
}
__device__ __forceinline__ u64 add2(u64 a, u64 b) {
    u64 r; asm("add.rn.f32x2 %0, %1, %2;" : "=l"(r) : "l"(a), "l"(b)); return r;
}
__device__ __forceinline__ u64 mul2(u64 a, u64 b) {
    u64 r; asm("mul.rn.f32x2 %0, %1, %2;" : "=l"(r) : "l"(a), "l"(b)); return r;
}
__device__ __forceinline__ u64 fma2(u64 a, u64 b, u64 c) {
    u64 r; asm("fma.rn.f32x2 %0, %1, %2, %3;" : "=l"(r) : "l"(a), "l"(b), "l"(c)); return r;
}

#define INS5(s, j, D0, D1, D2, D3, D4, I0, I1, I2, I3, I4)                             \
    if ((s) < D4) {                                                                    \
        D4 = (s); I4 = (j);                                                            \
        if (D4 < D3) { float t = D3; D3 = D4; D4 = t; int ti = I3; I3 = I4; I4 = ti; } \
        if (D3 < D2) { float t = D2; D2 = D3; D3 = t; int ti = I2; I2 = I3; I3 = ti; } \
        if (D2 < D1) { float t = D1; D1 = D2; D2 = t; int ti = I1; I1 = I2; I2 = ti; } \
        if (D1 < D0) { float t = D0; D0 = D1; D1 = t; int ti = I0; I0 = I1; I1 = ti; } \
    }

__global__ __launch_bounds__(TPB) void upsample_flow(
    const float* __restrict__ xyz,
    const float* __restrict__ sxyz,
    const float* __restrict__ sflow,
    const int* __restrict__ resol_ptr,
    const int* __restrict__ K_ptr,
    float* __restrict__ out)
{
    __shared__ __align__(16) float sx[MDIM];
    __shared__ __align__(16) float sy[MDIM];
    __shared__ __align__(16) float sz[MDIM];

    const int b   = blockIdx.y;
    const int n   = blockIdx.x * TPB + threadIdx.x;
    const int tid = threadIdx.x;

    const int sbase = b * 3 * MDIM;
    #pragma unroll
    for (int i = tid; i < MDIM; i += TPB) {
        sx[i] = sxyz[sbase + i];
        sy[i] = sxyz[sbase + MDIM + i];
        sz[i] = sxyz[sbase + 2 * MDIM + i];
    }
    __syncthreads();

    const int qbase = b * 3 * NDIM;
    const float qx = xyz[qbase + n];
    const float qy = xyz[qbase + NDIM + n];
    const float qz = xyz[qbase + 2 * NDIM + n];

    const int   K      = *K_ptr;
    const float sigma  = (float)(*resol_ptr);   // INITIAL_RADIUS = 1.0
    const float inv_s2 = 1.0f / (sigma * sigma);

    if (K == 5) {
        // packed (-q, -q) for each coordinate: dx = px + (-qx) == px - qx exactly
        const u64 nqx2 = pk2(-qx, -qx);
        const u64 nqy2 = pk2(-qy, -qy);
        const u64 nqz2 = pk2(-qz, -qz);

        float d0 = CUDART_INF_F, d1 = CUDART_INF_F, d2 = CUDART_INF_F,
              d3 = CUDART_INF_F, d4 = CUDART_INF_F;
        int   i0 = 0, i1 = 0, i2 = 0, i3 = 0, i4 = 0;

        const ulonglong2* X2 = (const ulonglong2*)sx;  // each elem = 4 floats
        const ulonglong2* Y2 = (const ulonglong2*)sy;
        const ulonglong2* Z2 = (const ulonglong2*)sz;

        #pragma unroll 4
        for (int g = 0; g < MDIM / 4; ++g) {
            const ulonglong2 xv = X2[g];   // LDS.128 (broadcast)
            const ulonglong2 yv = Y2[g];
            const ulonglong2 zv = Z2[g];

            const u64 dx01 = add2(xv.x, nqx2);
            const u64 dx23 = add2(xv.y, nqx2);
            const u64 dy01 = add2(yv.x, nqy2);
            const u64 dy23 = add2(yv.y, nqy2);
            const u64 dz01 = add2(zv.x, nqz2);
            const u64 dz23 = add2(zv.y, nqz2);

            u64 s01 = mul2(dx01, dx01);
            s01 = fma2(dy01, dy01, s01);
            s01 = fma2(dz01, dz01, s01);
            u64 s23 = mul2(dx23, dx23);
            s23 = fma2(dy23, dy23, s23);
            s23 = fma2(dz23, dz23, s23);

            float s0, s1, s2, s3;
            upk2(s01, s0, s1);
            upk2(s23, s2, s3);

            const float m = fminf(fminf(s0, s1), fminf(s2, s3));
            if (m < d4) {
                const int jb = 4 * g;
                INS5(s0, jb,     d0, d1, d2, d3, d4, i0, i1, i2, i3, i4);
                INS5(s1, jb + 1, d0, d1, d2, d3, d4, i0, i1, i2, i3, i4);
                INS5(s2, jb + 2, d0, d1, d2, d3, d4, i0, i1, i2, i3, i4);
                INS5(s3, jb + 3, d0, d1, d2, d3, d4, i0, i1, i2, i3, i4);
            }
        }

        const float e0 = sqrtf(fmaxf(d0 * inv_s2, 1e-12f));
        const float e1 = sqrtf(fmaxf(d1 * inv_s2, 1e-12f));
        const float e2 = sqrtf(fmaxf(d2 * inv_s2, 1e-12f));
        const float e3 = sqrtf(fmaxf(d3 * inv_s2, 1e-12f));
        const float e4 = sqrtf(fmaxf(d4 * inv_s2, 1e-12f));
        const float em = e0;  // sorted ascending

        const float w0 = __expf(em - e0);
        const float w1 = __expf(em - e1);
        const float w2 = __expf(em - e2);
        const float w3 = __expf(em - e3);
        const float w4 = __expf(em - e4);
        const float inv_w = 1.0f / (w0 + w1 + w2 + w3 + w4);

        const float* f0 = sflow + sbase;
        const float* f1 = f0 + MDIM;
        const float* f2 = f1 + MDIM;
        const float fx = w0*f0[i0] + w1*f0[i1] + w2*f0[i2] + w3*f0[i3] + w4*f0[i4];
        const float fy = w0*f1[i0] + w1*f1[i1] + w2*f1[i2] + w3*f1[i3] + w4*f1[i4];
        const float fz = w0*f2[i0] + w1*f2[i1] + w2*f2[i2] + w3*f2[i3] + w4*f2[i4];

        out[qbase + n]            = fx * inv_w;
        out[qbase + NDIM + n]     = fy * inv_w;
        out[qbase + 2 * NDIM + n] = fz * inv_w;
    } else {
        // ---- generic fallback, K <= 32 (exact; correctness only) ----
        const int KK = (K < 32) ? K : 32;
        float dl[32];
        int   il[32];
        for (int k = 0; k < KK; ++k) { dl[k] = CUDART_INF_F; il[k] = 0; }
        for (int j = 0; j < MDIM; ++j) {
            const float dx = sx[j] - qx;
            const float dy = sy[j] - qy;
            const float dz = sz[j] - qz;
            const float sq = fmaf(dx, dx, fmaf(dy, dy, dz * dz));
            if (sq < dl[KK - 1]) {
                int k = KK - 1;
                while (k > 0 && dl[k - 1] > sq) {
                    dl[k] = dl[k - 1]; il[k] = il[k - 1]; --k;
                }
                dl[k] = sq; il[k] = j;
            }
        }
        const float em = sqrtf(fmaxf(dl[0] * inv_s2, 1e-12f));
        float fx = 0.f, fy = 0.f, fz = 0.f, wsum = 0.f;
        for (int k = 0; k < KK; ++k) {
            const float e = sqrtf(fmaxf(dl[k] * inv_s2, 1e-12f));
            const float w = __expf(em - e);
            wsum += w;
            const int idx = il[k];
            fx += w * sflow[sbase + idx];
            fy += w * sflow[sbase + MDIM + idx];
            fz += w * sflow[sbase + 2 * MDIM + idx];
        }
        const float inv_w = 1.0f / wsum;
        out[qbase + n]            = fx * inv_w;
        out[qbase + NDIM + n]     = fy * inv_w;
        out[qbase + 2 * NDIM + n] = fz * inv_w;
    }
}

extern "C" void kernel_launch(void* const* d_in, const int* in_sizes, int n_in,
                              void* d_out, int out_size)
{
    const float* xyz   = (const float*)d_in[0];
    const float* sxyz  = (const float*)d_in[1];
    const float* sflow = (const float*)d_in[2];
    const int*   resol = (const int*)d_in[3];
    const int*   Kp    = (const int*)d_in[4];
    float* out = (float*)d_out;

    dim3 grid(NDIM / TPB, BDIM);
    upsample_flow<<<grid, TPB>>>(xyz, sxyz, sflow, resol, Kp, out);
}